// round 6
// baseline (speedup 1.0000x reference)
#include <cuda_runtime.h>
#include <math.h>

#define IC    1024
#define MIDC  512
#define HH    38
#define WW    50
#define HW    1900
#define NA    17100
#define NS    32768
#define PRE   6000
#define POST  300

// ---------------- static device scratch ----------------
__device__ float g_x[2*MIDC*HW];            // conv out (post-ReLU), NCHW
__device__ float g_cls[2*18*HW];            // cls logits
__device__ float g_reg[2*36*HW];            // reg deltas
__device__ float g_boxes[2*NA*4];           // clipped proposal boxes
__device__ unsigned long long g_keys[2*NS]; // sort keys
__device__ float g_topb[2*PRE*4];           // top-6000 boxes (sorted)
__device__ int   g_sel[2*POST];             // NMS kept indices
__device__ float g_ov[(size_t)2*NA*20];     // masked IoU matrix
__device__ float g_maxov[2*NA];
__device__ int   g_amax[2*NA];
__device__ int   g_gtmax[2*20];             // per-GT max IoU (float bits as int)
__device__ int   g_labels[2*NA];
__device__ int   g_cnt[2];                  // n_ex per batch

// 9 base anchors (ratios 0.5/1/2 x scales 8/16/32), verified vs reference
__constant__ float c_anc[9][4] = {
 {-84.f,-40.f,99.f,55.f},{-176.f,-88.f,191.f,103.f},{-360.f,-184.f,375.f,199.f},
 {-56.f,-56.f,71.f,71.f},{-120.f,-120.f,135.f,135.f},{-248.f,-248.f,263.f,263.f},
 {-36.f,-80.f,51.f,95.f},{-80.f,-168.f,95.f,183.f},{-168.f,-344.f,183.f,359.f}};

__global__ void init_kernel() {
    int t = threadIdx.x;
    if (t < 40) g_gtmax[t] = (int)0xBF800000u; // -1.0f bits
}

// Neumaier compensated accumulate: sum/cmp += p. All intrinsics -> no contraction.
#define KAHAN_ADD(sum, cmp, p) do {                         \
    float _t = __fadd_rn(sum, p);                           \
    float _z = __fsub_rn(_t, sum);                          \
    cmp = __fadd_rn(cmp, __fadd_rn(                         \
            __fsub_rn(sum, __fsub_rn(_t, _z)),              \
            __fsub_rn(p, _z)));                             \
    sum = _t;                                               \
} while (0)

// ---------------- 3x3 conv 1024->512 + bias + ReLU (compensated accumulation) ---
// Logits accurate to ~1e-7 -> selection ordering equals true ordering.
__global__ __launch_bounds__(256) void conv3_kernel(
    const float* __restrict__ feat, const float* __restrict__ wc,
    const float* __restrict__ bc)
{
    __shared__ float sW[64][73];     // [oc][ic8*9+tap]
    __shared__ float sI[8][4][34];   // [ic8][row][col]
    int tid = threadIdx.x;
    int tx = tid & 15, ty = tid >> 4;
    int tileC = blockIdx.x & 1, tileR = blockIdx.x >> 1;
    int ocBase = blockIdx.y << 6;
    int b = blockIdx.z;
    int y0 = tileR * 2, x0 = tileC * 32;
    int r = tx >> 3, cq = (tx & 7) << 2;

    float acc[4][4], cmp[4][4];
    #pragma unroll
    for (int q = 0; q < 4; ++q)
        #pragma unroll
        for (int c = 0; c < 4; ++c) { acc[q][c] = 0.f; cmp[q][c] = 0.f; }

    const float* wbase = wc + (size_t)ocBase * (IC*9);
    for (int icb = 0; icb < IC; icb += 8) {
        #pragma unroll
        for (int s = tid; s < 64*72; s += 256) {
            int oc = s / 72, k = s % 72;
            sW[oc][k] = wbase[(size_t)oc*(IC*9) + icb*9 + k];
        }
        #pragma unroll
        for (int s = tid; s < 1088; s += 256) {
            int ic = s / 136, rem = s % 136, rr = rem / 34, cc = rem % 34;
            int y = y0 - 1 + rr, x = x0 - 1 + cc;
            float v = 0.f;
            if (y >= 0 && y < HH && x >= 0 && x < WW)
                v = feat[(((size_t)b*IC + icb + ic)*HH + y)*WW + x];
            sI[ic][rr][cc] = v;
        }
        __syncthreads();
        #pragma unroll 2
        for (int ic8 = 0; ic8 < 8; ++ic8) {
            #pragma unroll
            for (int ky = 0; ky < 3; ++ky) {
                #pragma unroll
                for (int kx = 0; kx < 3; ++kx) {
                    int k = ic8*9 + ky*3 + kx;
                    float b0 = sI[ic8][r+ky][cq+kx+0];
                    float b1 = sI[ic8][r+ky][cq+kx+1];
                    float b2 = sI[ic8][r+ky][cq+kx+2];
                    float b3 = sI[ic8][r+ky][cq+kx+3];
                    #pragma unroll
                    for (int q = 0; q < 4; ++q) {
                        float a = sW[ty*4+q][k];
                        float p0 = __fmul_rn(a, b0);
                        float p1 = __fmul_rn(a, b1);
                        float p2 = __fmul_rn(a, b2);
                        float p3 = __fmul_rn(a, b3);
                        KAHAN_ADD(acc[q][0], cmp[q][0], p0);
                        KAHAN_ADD(acc[q][1], cmp[q][1], p1);
                        KAHAN_ADD(acc[q][2], cmp[q][2], p2);
                        KAHAN_ADD(acc[q][3], cmp[q][3], p3);
                    }
                }
            }
        }
        __syncthreads();
    }
    int y = y0 + r;
    #pragma unroll
    for (int q = 0; q < 4; ++q) {
        int oc = ocBase + ty*4 + q;
        float bias = bc[oc];
        #pragma unroll
        for (int c = 0; c < 4; ++c) {
            int x = x0 + cq + c;
            if (x < WW) {
                float v = __fadd_rn(__fadd_rn(acc[q][c], cmp[q][c]), bias);
                g_x[(((size_t)b*MIDC + oc)*HH + y)*WW + x] = fmaxf(v, 0.f);
            }
        }
    }
}

// ---------------- 1x1 heads: compensated sequential dot per output channel ------
__global__ __launch_bounds__(64) void heads_kernel(
    const float* __restrict__ wcl, const float* __restrict__ bcl,
    const float* __restrict__ wrg, const float* __restrict__ brg)
{
    __shared__ float sx[MIDC];
    int bhw = blockIdx.x;
    int b = bhw / HW, hw = bhw % HW;
    int tid = threadIdx.x;
    for (int k = tid; k < MIDC; k += 64)
        sx[k] = g_x[((size_t)b*MIDC + k)*HW + hw];
    __syncthreads();
    if (tid >= 54) return;
    const float* wr = (tid < 18) ? (wcl + tid*MIDC) : (wrg + (tid-18)*MIDC);
    float acc = 0.f, cmp = 0.f;
    #pragma unroll 4
    for (int k = 0; k < MIDC; ++k) {
        float p = __fmul_rn(wr[k], sx[k]);
        KAHAN_ADD(acc, cmp, p);
    }
    float v = __fadd_rn(acc, cmp);
    if (tid < 18)
        g_cls[((size_t)b*18 + tid)*HW + hw] = v + bcl[tid];
    else
        g_reg[((size_t)b*36 + (tid-18))*HW + hw] = v + brg[tid-18];
}

// ---------------- score + box transform + clip + sort key (R4 style: plain ops) -
__global__ void scorebox_kernel(const float* __restrict__ info) {
    int i = blockIdx.x * blockDim.x + threadIdx.x;
    int b = blockIdx.y;
    if (i >= NS) return;
    if (i >= NA) { g_keys[(size_t)b*NS + i] = 0ull; return; }
    int a = i % 9, hw = i / 9, h = hw / WW, w = hw % WW;
    float s0 = g_cls[((size_t)b*18 + a)*HW + hw];
    float s1 = g_cls[((size_t)b*18 + 9 + a)*HW + hw];
    float m = fmaxf(s0, s1);
    float e0 = expf(s0 - m), e1 = expf(s1 - m);
    float score = e1 / (e0 + e1);
    float d0 = g_reg[((size_t)b*36 + a*4 + 0)*HW + hw];
    float d1 = g_reg[((size_t)b*36 + a*4 + 1)*HW + hw];
    float d2 = g_reg[((size_t)b*36 + a*4 + 2)*HW + hw];
    float d3 = g_reg[((size_t)b*36 + a*4 + 3)*HW + hw];
    float gx = w * 16.f, gy = h * 16.f;
    float ax1 = c_anc[a][0] + gx, ay1 = c_anc[a][1] + gy;
    float ax2 = c_anc[a][2] + gx, ay2 = c_anc[a][3] + gy;
    float wA = ax2 - ax1 + 1.f, hA = ay2 - ay1 + 1.f;
    float cx = ax1 + 0.5f*wA, cy = ay1 + 0.5f*hA;
    float pcx = d0*wA + cx, pcy = d1*hA + cy;
    float pw = expf(d2)*wA, ph = expf(d3)*hA;
    float imh = info[b*3+0] - 1.f, imw = info[b*3+1] - 1.f;
    float mins = 16.f * info[b*3+2];
    float x1 = fminf(fmaxf(pcx - 0.5f*pw, 0.f), imw);
    float y1 = fminf(fmaxf(pcy - 0.5f*ph, 0.f), imh);
    float x2 = fminf(fmaxf(pcx + 0.5f*pw, 0.f), imw);
    float y2 = fminf(fmaxf(pcy + 0.5f*ph, 0.f), imh);
    bool valid = (x2 - x1 + 1.f >= mins) && (y2 - y1 + 1.f >= mins);
    float sc = valid ? score : -1000000000.0f;
    size_t bo = ((size_t)b*NA + i)*4;
    g_boxes[bo+0] = x1; g_boxes[bo+1] = y1; g_boxes[bo+2] = x2; g_boxes[bo+3] = y2;
    unsigned u = __float_as_uint(sc);
    u = (u & 0x80000000u) ? ~u : (u | 0x80000000u);
    g_keys[(size_t)b*NS + i] =
        ((unsigned long long)u << 32) | (unsigned long long)(0xFFFFFFFFu - (unsigned)i);
}

// ---------------- bitonic sort, descending, 32768 keys per batch ----------------
__global__ void sort_local_kernel() {
    __shared__ unsigned long long s[4096];
    int b = blockIdx.y, base = blockIdx.x * 4096;
    unsigned long long* g = g_keys + (size_t)b*NS + base;
    for (int e = threadIdx.x; e < 4096; e += blockDim.x) s[e] = g[e];
    __syncthreads();
    for (int k = 2; k <= 4096; k <<= 1) {
        for (int j = k >> 1; j > 0; j >>= 1) {
            for (int e = threadIdx.x; e < 4096; e += blockDim.x) {
                int ixj = e ^ j;
                if (ixj > e) {
                    bool fl = (((base + e) & k) == 0);
                    unsigned long long A = s[e], B = s[ixj];
                    if ((A < B) == fl) { s[e] = B; s[ixj] = A; }
                }
            }
            __syncthreads();
        }
    }
    for (int e = threadIdx.x; e < 4096; e += blockDim.x) g[e] = s[e];
}

__global__ void sort_global_kernel(int k, int j) {
    int b = blockIdx.y;
    int e = blockIdx.x * blockDim.x + threadIdx.x;
    if (e >= NS) return;
    int ixj = e ^ j;
    if (ixj <= e) return;
    unsigned long long* g = g_keys + (size_t)b*NS;
    unsigned long long A = g[e], B = g[ixj];
    bool fl = ((e & k) == 0);
    if ((A < B) == fl) { g[e] = B; g[ixj] = A; }
}

__global__ void sort_merge_kernel(int k) {
    __shared__ unsigned long long s[4096];
    int b = blockIdx.y, base = blockIdx.x * 4096;
    unsigned long long* g = g_keys + (size_t)b*NS + base;
    for (int e = threadIdx.x; e < 4096; e += blockDim.x) s[e] = g[e];
    __syncthreads();
    for (int j = 2048; j > 0; j >>= 1) {
        for (int e = threadIdx.x; e < 4096; e += blockDim.x) {
            int ixj = e ^ j;
            if (ixj > e) {
                bool fl = (((base + e) & k) == 0);
                unsigned long long A = s[e], B = s[ixj];
                if ((A < B) == fl) { s[e] = B; s[ixj] = A; }
            }
        }
        __syncthreads();
    }
    for (int e = threadIdx.x; e < 4096; e += blockDim.x) g[e] = s[e];
}

__global__ void gather_top_kernel() {
    int t = blockIdx.x * blockDim.x + threadIdx.x;
    if (t >= 2*PRE) return;
    int b = t / PRE, r = t % PRE;
    unsigned long long key = g_keys[(size_t)b*NS + r];
    unsigned idx = 0xFFFFFFFFu - (unsigned)(key & 0xFFFFFFFFu);
    size_t src = ((size_t)b*NA + idx)*4, dst = ((size_t)b*PRE + r)*4;
    g_topb[dst+0] = g_boxes[src+0]; g_topb[dst+1] = g_boxes[src+1];
    g_topb[dst+2] = g_boxes[src+2]; g_topb[dst+3] = g_boxes[src+3];
}

// ---------------- greedy NMS, 1 block/batch, early exit after 300 kept -----------
__global__ void nms_kernel() {
    int b = blockIdx.x, tid = threadIdx.x;
    __shared__ unsigned rm[(PRE + 31)/32];
    for (int k = tid; k < (PRE+31)/32; k += blockDim.x) rm[k] = 0u;
    __syncthreads();
    const float* B = g_topb + (size_t)b*PRE*4;
    int cnt = 0;
    for (int i = 0; i < PRE; ++i) {
        if ((rm[i >> 5] >> (i & 31)) & 1u) continue;
        if (tid == 0 && cnt < POST) g_sel[b*POST + cnt] = i;
        cnt++;
        if (cnt >= POST) break;
        float cx1 = B[i*4+0], cy1 = B[i*4+1], cx2 = B[i*4+2], cy2 = B[i*4+3];
        float ca = (cx2 - cx1 + 1.f) * (cy2 - cy1 + 1.f);
        for (int j = i + 1 + tid; j < PRE; j += blockDim.x) {
            float x1 = B[j*4+0], y1 = B[j*4+1], x2 = B[j*4+2], y2 = B[j*4+3];
            float iw = fmaxf(fminf(cx2, x2) - fmaxf(cx1, x1) + 1.f, 0.f);
            float ih = fmaxf(fminf(cy2, y2) - fmaxf(cy1, y1) + 1.f, 0.f);
            float inter = iw * ih;
            float iou = inter / (ca + (x2 - x1 + 1.f)*(y2 - y1 + 1.f) - inter);
            if (iou > 0.7f) atomicOr(&rm[j >> 5], 1u << (j & 31));
        }
        __syncthreads();
    }
    for (int k = cnt + tid; k < POST; k += blockDim.x) g_sel[b*POST + k] = 0;
}

__global__ void rois_kernel(float* __restrict__ out) {
    int t = blockIdx.x * blockDim.x + threadIdx.x;
    if (t >= 2*POST) return;
    int b = t / POST, k = t % POST;
    int i = g_sel[b*POST + k];
    size_t o = ((size_t)b*POST + k)*5;
    size_t src = ((size_t)b*PRE + i)*4;
    out[o+0] = (float)b;
    out[o+1] = g_topb[src+0]; out[o+2] = g_topb[src+1];
    out[o+3] = g_topb[src+2]; out[o+4] = g_topb[src+3];
}

// ---------------- anchor target: masked IoU, per-anchor max/argmax, per-GT max ---
__global__ void iou_kernel(const float* __restrict__ gt, const float* __restrict__ info) {
    int b = blockIdx.y;
    int i = blockIdx.x * blockDim.x + threadIdx.x;
    __shared__ float sgt[20][4];
    if (threadIdx.x < 80)
        ((float*)sgt)[threadIdx.x] = gt[b*100 + (threadIdx.x/4)*5 + (threadIdx.x%4)];
    __syncthreads();
    float infoH = info[b*3+0], infoW = info[b*3+1];
    bool act = i < NA;
    int a = act ? i % 9 : 0, hw = act ? i / 9 : 0;
    float gx = (hw % WW) * 16.f, gy = (hw / WW) * 16.f;
    float ax1 = c_anc[a][0]+gx, ay1 = c_anc[a][1]+gy, ax2 = c_anc[a][2]+gx, ay2 = c_anc[a][3]+gy;
    bool inside = act && (ax1 >= 0.f) && (ay1 >= 0.f) && (ax2 < infoW) && (ay2 < infoH);
    float areaA = (ax2 - ax1 + 1.f) * (ay2 - ay1 + 1.f);
    float best = -1e30f; int bi = 0;
    for (int g = 0; g < 20; ++g) {
        float bx1 = sgt[g][0], by1 = sgt[g][1], bx2 = sgt[g][2], by2 = sgt[g][3];
        float iw = fmaxf(fminf(ax2, bx2) - fmaxf(ax1, bx1) + 1.f, 0.f);
        float ih = fmaxf(fminf(ay2, by2) - fmaxf(ay1, by1) + 1.f, 0.f);
        float inter = iw * ih;
        float areaB = (bx2 - bx1 + 1.f) * (by2 - by1 + 1.f);
        float v = inter / (areaA + areaB - inter);
        v = inside ? v : -1.0f;
        if (act) {
            g_ov[((size_t)b*NA + i)*20 + g] = v;
            if (v > best) { best = v; bi = g; }
        }
        float vm = act ? v : -2.0f;
        #pragma unroll
        for (int off = 16; off; off >>= 1) vm = fmaxf(vm, __shfl_xor_sync(0xffffffffu, vm, off));
        if ((threadIdx.x & 31) == 0 && vm > 0.f)
            atomicMax(&g_gtmax[b*20 + g], __float_as_int(vm));
    }
    if (act) { g_maxov[(size_t)b*NA + i] = best; g_amax[(size_t)b*NA + i] = bi; }
}

__global__ void labels_kernel() {
    int b = blockIdx.y;
    int i = blockIdx.x * blockDim.x + threadIdx.x;
    if (i >= NA) return;
    float best = g_maxov[(size_t)b*NA + i];
    bool inside = g_ov[((size_t)b*NA + i)*20 + 0] >= 0.f;
    int lbl = -1;
    if (inside) {
        if (best < 0.3f) lbl = 0;
        bool isgt = false;
        for (int g = 0; g < 20; ++g) {
            float gm = __int_as_float(g_gtmax[b*20 + g]);
            if (gm > 0.f && g_ov[((size_t)b*NA + i)*20 + g] == gm) isgt = true;
        }
        if (isgt) lbl = 1;
        if (best >= 0.7f) lbl = 1;
    }
    g_labels[(size_t)b*NA + i] = lbl;
}

// ---------------- fg/bg subsample via inclusive block scan (1024 threads) --------
__global__ void cap_kernel() {
    int b = blockIdx.x;
    int tid = threadIdx.x, lane = tid & 31, wid = tid >> 5;
    __shared__ int wsum[32];
    __shared__ int s_carry, s_fg;
    int* lab = g_labels + (size_t)b*NA;
    if (tid == 0) s_carry = 0;
    __syncthreads();
    for (int base = 0; base < NA; base += 1024) {
        int i = base + tid;
        int f = (i < NA && lab[i] == 1) ? 1 : 0;
        int v = f;
        #pragma unroll
        for (int d = 1; d < 32; d <<= 1) { int n = __shfl_up_sync(0xffffffffu, v, d); if (lane >= d) v += n; }
        if (lane == 31) wsum[wid] = v;
        __syncthreads();
        if (wid == 0) {
            int t2 = wsum[lane];
            #pragma unroll
            for (int d = 1; d < 32; d <<= 1) { int n = __shfl_up_sync(0xffffffffu, t2, d); if (lane >= d) t2 += n; }
            wsum[lane] = t2;
        }
        __syncthreads();
        int pre = v + (wid ? wsum[wid-1] : 0) + s_carry;
        if (f && pre > 128) lab[i] = -1;
        __syncthreads();
        if (tid == 0) s_carry += wsum[31];
        __syncthreads();
    }
    if (tid == 0) { s_fg = min(s_carry, 128); s_carry = 0; }
    __syncthreads();
    int num_bg = 256 - s_fg;
    for (int base = 0; base < NA; base += 1024) {
        int i = base + tid;
        int f = (i < NA && lab[i] == 0) ? 1 : 0;
        int v = f;
        #pragma unroll
        for (int d = 1; d < 32; d <<= 1) { int n = __shfl_up_sync(0xffffffffu, v, d); if (lane >= d) v += n; }
        if (lane == 31) wsum[wid] = v;
        __syncthreads();
        if (wid == 0) {
            int t2 = wsum[lane];
            #pragma unroll
            for (int d = 1; d < 32; d <<= 1) { int n = __shfl_up_sync(0xffffffffu, t2, d); if (lane >= d) t2 += n; }
            wsum[lane] = t2;
        }
        __syncthreads();
        int pre = v + (wid ? wsum[wid-1] : 0) + s_carry;
        if (f && pre > num_bg) lab[i] = -1;
        __syncthreads();
        if (tid == 0) s_carry += wsum[31];
        __syncthreads();
    }
    if (tid == 0) g_cnt[b] = s_fg + min(s_carry, num_bg);
}

// ---------------- losses: deterministic single-block reduction ----------------
__global__ void loss_kernel(float* __restrict__ out, const float* __restrict__ gt) {
    int tid = threadIdx.x;
    __shared__ float scl[1024], sr0[1024], sr1[1024];
    float cl = 0.f, r0 = 0.f, r1 = 0.f;
    for (int t = tid; t < 2*NA; t += 1024) {
        int b = t / NA, i = t % NA;
        int lab = g_labels[(size_t)b*NA + i];
        if (lab == -1) continue;
        int a = i % 9, hw = i / 9;
        float s0 = g_cls[((size_t)b*18 + a)*HW + hw];
        float s1 = g_cls[((size_t)b*18 + 9 + a)*HW + hw];
        float m = fmaxf(s0, s1);
        float lse = m + logf(expf(s0 - m) + expf(s1 - m));
        cl += (lab ? s1 : s0) - lse;
        if (lab == 1) {
            float gx = (hw % WW) * 16.f, gy = (hw / WW) * 16.f;
            float ax1 = c_anc[a][0]+gx, ay1 = c_anc[a][1]+gy;
            float ax2 = c_anc[a][2]+gx, ay2 = c_anc[a][3]+gy;
            float ew = ax2-ax1+1.f, eh = ay2-ay1+1.f;
            float ecx = ax1 + 0.5f*ew, ecy = ay1 + 0.5f*eh;
            int g = g_amax[(size_t)b*NA + i];
            const float* G = gt + b*100 + g*5;
            float gw = G[2]-G[0]+1.f, gh = G[3]-G[1]+1.f;
            float gcx = G[0]+0.5f*gw, gcy = G[1]+0.5f*gh;
            float tgt[4] = { (gcx-ecx)/ew, (gcy-ecy)/eh, logf(gw/ew), logf(gh/eh) };
            float s = 0.f;
            #pragma unroll
            for (int j = 0; j < 4; ++j) {
                float p = g_reg[((size_t)b*36 + a*4 + j)*HW + hw];
                float d = p - tgt[j];
                float ad = fabsf(d);
                s += (ad < 1.f/9.f) ? 4.5f*d*d : (ad - 1.f/18.f);
            }
            if (b) r1 += s; else r0 += s;
        }
    }
    scl[tid] = cl; sr0[tid] = r0; sr1[tid] = r1;
    __syncthreads();
    for (int s = 512; s; s >>= 1) {
        if (tid < s) { scl[tid]+=scl[tid+s]; sr0[tid]+=sr0[tid+s]; sr1[tid]+=sr1[tid+s]; }
        __syncthreads();
    }
    if (tid == 0) {
        int cnt = g_cnt[0] + g_cnt[1];
        out[2*POST*5 + 0] = -scl[0] / (float)max(cnt, 1);
        float ne0 = fmaxf((float)g_cnt[0], 1.f), ne1 = fmaxf((float)g_cnt[1], 1.f);
        out[2*POST*5 + 1] = 0.5f * (sr0[0]/ne0 + sr1[0]/ne1);
    }
}

extern "C" void kernel_launch(void* const* d_in, const int* in_sizes, int n_in,
                              void* d_out, int out_size) {
    const float* feat = (const float*)d_in[0];
    const float* gt   = (const float*)d_in[1];
    const float* info = (const float*)d_in[2];
    const float* wc   = (const float*)d_in[3];
    const float* bc   = (const float*)d_in[4];
    const float* wcl  = (const float*)d_in[5];
    const float* bcl  = (const float*)d_in[6];
    const float* wrg  = (const float*)d_in[7];
    const float* brg  = (const float*)d_in[8];
    float* out = (float*)d_out;

    init_kernel<<<1, 64>>>();
    conv3_kernel<<<dim3(38, 8, 2), 256>>>(feat, wc, bc);
    heads_kernel<<<2*HW, 64>>>(wcl, bcl, wrg, brg);
    scorebox_kernel<<<dim3(NS/256, 2), 256>>>(info);
    sort_local_kernel<<<dim3(8, 2), 512>>>();
    for (int k = 8192; k <= NS; k <<= 1) {
        for (int j = k >> 1; j >= 4096; j >>= 1)
            sort_global_kernel<<<dim3(NS/256, 2), 256>>>(k, j);
        sort_merge_kernel<<<dim3(8, 2), 512>>>(k);
    }
    gather_top_kernel<<<(2*PRE + 255)/256, 256>>>();
    nms_kernel<<<2, 256>>>();
    rois_kernel<<<3, 256>>>(out);
    iou_kernel<<<dim3((NA + 255)/256, 2), 256>>>(gt, info);
    labels_kernel<<<dim3((NA + 255)/256, 2), 256>>>();
    cap_kernel<<<2, 1024>>>();
    loss_kernel<<<1, 1024>>>(out, gt);
}

// round 15
// speedup vs baseline: 2.2798x; 2.2798x over previous
#include <cuda_runtime.h>
#include <math.h>

#define IC    1024
#define MIDC  512
#define HH    38
#define WW    50
#define HW    1900
#define NA    17100
#define NS    32768
#define PRE   6000
#define POST  300

// ---------------- static device scratch ----------------
__device__ float g_x[2*MIDC*HW];            // conv out (post-ReLU), NCHW
__device__ float g_cls[2*18*HW];            // cls logits
__device__ float g_reg[2*36*HW];            // reg deltas
__device__ float g_boxes[2*NA*4];           // clipped proposal boxes
__device__ unsigned long long g_keys[2*NS]; // sort keys
__device__ float g_topb[2*PRE*4];           // top-6000 boxes (sorted)
__device__ int   g_sel[2*POST];             // NMS kept indices
__device__ float g_ov[(size_t)2*NA*20];     // masked IoU matrix
__device__ float g_maxov[2*NA];
__device__ int   g_amax[2*NA];
__device__ int   g_gtmax[2*20];             // per-GT max IoU (float bits as int)
__device__ int   g_labels[2*NA];
__device__ int   g_cnt[2];                  // n_ex per batch

// 9 base anchors (ratios 0.5/1/2 x scales 8/16/32), verified vs reference
__constant__ float c_anc[9][4] = {
 {-84.f,-40.f,99.f,55.f},{-176.f,-88.f,191.f,103.f},{-360.f,-184.f,375.f,199.f},
 {-56.f,-56.f,71.f,71.f},{-120.f,-120.f,135.f,135.f},{-248.f,-248.f,263.f,263.f},
 {-36.f,-80.f,51.f,95.f},{-80.f,-168.f,95.f,183.f},{-168.f,-344.f,183.f,359.f}};

__global__ void init_kernel() {
    int t = threadIdx.x;
    if (t < 40) g_gtmax[t] = (int)0xBF800000u; // -1.0f bits
}

// Neumaier compensated accumulate: sum/cmp += p. All intrinsics -> no contraction.
#define KAHAN_ADD(sum, cmp, p) do {                         \
    float _t = __fadd_rn(sum, p);                           \
    float _z = __fsub_rn(_t, sum);                          \
    cmp = __fadd_rn(cmp, __fadd_rn(                         \
            __fsub_rn(sum, __fsub_rn(_t, _z)),              \
            __fsub_rn(p, _z)));                             \
    sum = _t;                                               \
} while (0)

// ---------------- 3x3 conv 1024->512 + bias + ReLU -----------------------------
// Chunked FFMA (72 products per icb chunk, exact products) + Kahan across the
// 128 chunk sums -> ~6e-8 absolute logit error at ~1.07x plain-FFMA cost.
__global__ __launch_bounds__(256) void conv3_kernel(
    const float* __restrict__ feat, const float* __restrict__ wc,
    const float* __restrict__ bc)
{
    __shared__ float sW[64][73];     // [oc][ic8*9+tap]
    __shared__ float sI[8][4][34];   // [ic8][row][col]
    int tid = threadIdx.x;
    int tx = tid & 15, ty = tid >> 4;
    int tileC = blockIdx.x & 1, tileR = blockIdx.x >> 1;
    int ocBase = blockIdx.y << 6;
    int b = blockIdx.z;
    int y0 = tileR * 2, x0 = tileC * 32;
    int r = tx >> 3, cq = (tx & 7) << 2;

    float acc[4][4], cmp[4][4];
    #pragma unroll
    for (int q = 0; q < 4; ++q)
        #pragma unroll
        for (int c = 0; c < 4; ++c) { acc[q][c] = 0.f; cmp[q][c] = 0.f; }

    const float* wbase = wc + (size_t)ocBase * (IC*9);
    for (int icb = 0; icb < IC; icb += 8) {
        #pragma unroll
        for (int s = tid; s < 64*72; s += 256) {
            int oc = s / 72, k = s % 72;
            sW[oc][k] = wbase[(size_t)oc*(IC*9) + icb*9 + k];
        }
        #pragma unroll
        for (int s = tid; s < 1088; s += 256) {
            int ic = s / 136, rem = s % 136, rr = rem / 34, cc = rem % 34;
            int y = y0 - 1 + rr, x = x0 - 1 + cc;
            float v = 0.f;
            if (y >= 0 && y < HH && x >= 0 && x < WW)
                v = feat[(((size_t)b*IC + icb + ic)*HH + y)*WW + x];
            sI[ic][rr][cc] = v;
        }
        __syncthreads();
        // chunk accumulators (fresh per icb): plain FFMA, exact products
        float ch[4][4];
        #pragma unroll
        for (int q = 0; q < 4; ++q)
            #pragma unroll
            for (int c = 0; c < 4; ++c) ch[q][c] = 0.f;
        #pragma unroll 4
        for (int ic8 = 0; ic8 < 8; ++ic8) {
            #pragma unroll
            for (int ky = 0; ky < 3; ++ky) {
                #pragma unroll
                for (int kx = 0; kx < 3; ++kx) {
                    int k = ic8*9 + ky*3 + kx;
                    float b0 = sI[ic8][r+ky][cq+kx+0];
                    float b1 = sI[ic8][r+ky][cq+kx+1];
                    float b2 = sI[ic8][r+ky][cq+kx+2];
                    float b3 = sI[ic8][r+ky][cq+kx+3];
                    #pragma unroll
                    for (int q = 0; q < 4; ++q) {
                        float a = sW[ty*4+q][k];
                        ch[q][0] = __fmaf_rn(a, b0, ch[q][0]);
                        ch[q][1] = __fmaf_rn(a, b1, ch[q][1]);
                        ch[q][2] = __fmaf_rn(a, b2, ch[q][2]);
                        ch[q][3] = __fmaf_rn(a, b3, ch[q][3]);
                    }
                }
            }
        }
        // Kahan-fold chunk into the running compensated sum
        #pragma unroll
        for (int q = 0; q < 4; ++q)
            #pragma unroll
            for (int c = 0; c < 4; ++c)
                KAHAN_ADD(acc[q][c], cmp[q][c], ch[q][c]);
        __syncthreads();
    }
    int y = y0 + r;
    #pragma unroll
    for (int q = 0; q < 4; ++q) {
        int oc = ocBase + ty*4 + q;
        float bias = bc[oc];
        #pragma unroll
        for (int c = 0; c < 4; ++c) {
            int x = x0 + cq + c;
            if (x < WW) {
                float v = __fadd_rn(__fadd_rn(acc[q][c], cmp[q][c]), bias);
                g_x[(((size_t)b*MIDC + oc)*HH + y)*WW + x] = fmaxf(v, 0.f);
            }
        }
    }
}

// ---------------- 1x1 heads: chunked FFMA (32) + Kahan across 16 chunks ---------
__global__ __launch_bounds__(64) void heads_kernel(
    const float* __restrict__ wcl, const float* __restrict__ bcl,
    const float* __restrict__ wrg, const float* __restrict__ brg)
{
    __shared__ float sx[MIDC];
    int bhw = blockIdx.x;
    int b = bhw / HW, hw = bhw % HW;
    int tid = threadIdx.x;
    for (int k = tid; k < MIDC; k += 64)
        sx[k] = g_x[((size_t)b*MIDC + k)*HW + hw];
    __syncthreads();
    if (tid >= 54) return;
    const float* wr = (tid < 18) ? (wcl + tid*MIDC) : (wrg + (tid-18)*MIDC);
    float acc = 0.f, cmp = 0.f;
    for (int c0 = 0; c0 < MIDC; c0 += 32) {
        float ch = 0.f;
        #pragma unroll
        for (int k = 0; k < 32; ++k)
            ch = __fmaf_rn(wr[c0 + k], sx[c0 + k], ch);
        KAHAN_ADD(acc, cmp, ch);
    }
    float v = __fadd_rn(acc, cmp);
    if (tid < 18)
        g_cls[((size_t)b*18 + tid)*HW + hw] = v + bcl[tid];
    else
        g_reg[((size_t)b*36 + (tid-18))*HW + hw] = v + brg[tid-18];
}

// ---------------- score + box transform + clip + sort key ----------------------
__global__ void scorebox_kernel(const float* __restrict__ info) {
    int i = blockIdx.x * blockDim.x + threadIdx.x;
    int b = blockIdx.y;
    if (i >= NS) return;
    if (i >= NA) { g_keys[(size_t)b*NS + i] = 0ull; return; }
    int a = i % 9, hw = i / 9, h = hw / WW, w = hw % WW;
    float s0 = g_cls[((size_t)b*18 + a)*HW + hw];
    float s1 = g_cls[((size_t)b*18 + 9 + a)*HW + hw];
    float m = fmaxf(s0, s1);
    float e0 = expf(s0 - m), e1 = expf(s1 - m);
    float score = e1 / (e0 + e1);
    float d0 = g_reg[((size_t)b*36 + a*4 + 0)*HW + hw];
    float d1 = g_reg[((size_t)b*36 + a*4 + 1)*HW + hw];
    float d2 = g_reg[((size_t)b*36 + a*4 + 2)*HW + hw];
    float d3 = g_reg[((size_t)b*36 + a*4 + 3)*HW + hw];
    float gx = w * 16.f, gy = h * 16.f;
    float ax1 = c_anc[a][0] + gx, ay1 = c_anc[a][1] + gy;
    float ax2 = c_anc[a][2] + gx, ay2 = c_anc[a][3] + gy;
    float wA = ax2 - ax1 + 1.f, hA = ay2 - ay1 + 1.f;
    float cx = ax1 + 0.5f*wA, cy = ay1 + 0.5f*hA;
    float pcx = d0*wA + cx, pcy = d1*hA + cy;
    float pw = expf(d2)*wA, ph = expf(d3)*hA;
    float imh = info[b*3+0] - 1.f, imw = info[b*3+1] - 1.f;
    float mins = 16.f * info[b*3+2];
    float x1 = fminf(fmaxf(pcx - 0.5f*pw, 0.f), imw);
    float y1 = fminf(fmaxf(pcy - 0.5f*ph, 0.f), imh);
    float x2 = fminf(fmaxf(pcx + 0.5f*pw, 0.f), imw);
    float y2 = fminf(fmaxf(pcy + 0.5f*ph, 0.f), imh);
    bool valid = (x2 - x1 + 1.f >= mins) && (y2 - y1 + 1.f >= mins);
    float sc = valid ? score : -1000000000.0f;
    size_t bo = ((size_t)b*NA + i)*4;
    g_boxes[bo+0] = x1; g_boxes[bo+1] = y1; g_boxes[bo+2] = x2; g_boxes[bo+3] = y2;
    unsigned u = __float_as_uint(sc);
    u = (u & 0x80000000u) ? ~u : (u | 0x80000000u);
    g_keys[(size_t)b*NS + i] =
        ((unsigned long long)u << 32) | (unsigned long long)(0xFFFFFFFFu - (unsigned)i);
}

// ---------------- bitonic sort, descending, 32768 keys per batch ----------------
__global__ void sort_local_kernel() {
    __shared__ unsigned long long s[4096];
    int b = blockIdx.y, base = blockIdx.x * 4096;
    unsigned long long* g = g_keys + (size_t)b*NS + base;
    for (int e = threadIdx.x; e < 4096; e += blockDim.x) s[e] = g[e];
    __syncthreads();
    for (int k = 2; k <= 4096; k <<= 1) {
        for (int j = k >> 1; j > 0; j >>= 1) {
            for (int e = threadIdx.x; e < 4096; e += blockDim.x) {
                int ixj = e ^ j;
                if (ixj > e) {
                    bool fl = (((base + e) & k) == 0);
                    unsigned long long A = s[e], B = s[ixj];
                    if ((A < B) == fl) { s[e] = B; s[ixj] = A; }
                }
            }
            __syncthreads();
        }
    }
    for (int e = threadIdx.x; e < 4096; e += blockDim.x) g[e] = s[e];
}

__global__ void sort_global_kernel(int k, int j) {
    int b = blockIdx.y;
    int e = blockIdx.x * blockDim.x + threadIdx.x;
    if (e >= NS) return;
    int ixj = e ^ j;
    if (ixj <= e) return;
    unsigned long long* g = g_keys + (size_t)b*NS;
    unsigned long long A = g[e], B = g[ixj];
    bool fl = ((e & k) == 0);
    if ((A < B) == fl) { g[e] = B; g[ixj] = A; }
}

__global__ void sort_merge_kernel(int k) {
    __shared__ unsigned long long s[4096];
    int b = blockIdx.y, base = blockIdx.x * 4096;
    unsigned long long* g = g_keys + (size_t)b*NS + base;
    for (int e = threadIdx.x; e < 4096; e += blockDim.x) s[e] = g[e];
    __syncthreads();
    for (int j = 2048; j > 0; j >>= 1) {
        for (int e = threadIdx.x; e < 4096; e += blockDim.x) {
            int ixj = e ^ j;
            if (ixj > e) {
                bool fl = (((base + e) & k) == 0);
                unsigned long long A = s[e], B = s[ixj];
                if ((A < B) == fl) { s[e] = B; s[ixj] = A; }
            }
        }
        __syncthreads();
    }
    for (int e = threadIdx.x; e < 4096; e += blockDim.x) g[e] = s[e];
}

__global__ void gather_top_kernel() {
    int t = blockIdx.x * blockDim.x + threadIdx.x;
    if (t >= 2*PRE) return;
    int b = t / PRE, r = t % PRE;
    unsigned long long key = g_keys[(size_t)b*NS + r];
    unsigned idx = 0xFFFFFFFFu - (unsigned)(key & 0xFFFFFFFFu);
    size_t src = ((size_t)b*NA + idx)*4, dst = ((size_t)b*PRE + r)*4;
    g_topb[dst+0] = g_boxes[src+0]; g_topb[dst+1] = g_boxes[src+1];
    g_topb[dst+2] = g_boxes[src+2]; g_topb[dst+3] = g_boxes[src+3];
}

// ---------------- greedy NMS, 1 block/batch, early exit after 300 kept -----------
__global__ void nms_kernel() {
    int b = blockIdx.x, tid = threadIdx.x;
    __shared__ unsigned rm[(PRE + 31)/32];
    for (int k = tid; k < (PRE+31)/32; k += blockDim.x) rm[k] = 0u;
    __syncthreads();
    const float* B = g_topb + (size_t)b*PRE*4;
    int cnt = 0;
    for (int i = 0; i < PRE; ++i) {
        if ((rm[i >> 5] >> (i & 31)) & 1u) continue;
        if (tid == 0 && cnt < POST) g_sel[b*POST + cnt] = i;
        cnt++;
        if (cnt >= POST) break;
        float cx1 = B[i*4+0], cy1 = B[i*4+1], cx2 = B[i*4+2], cy2 = B[i*4+3];
        float ca = (cx2 - cx1 + 1.f) * (cy2 - cy1 + 1.f);
        for (int j = i + 1 + tid; j < PRE; j += blockDim.x) {
            float x1 = B[j*4+0], y1 = B[j*4+1], x2 = B[j*4+2], y2 = B[j*4+3];
            float iw = fmaxf(fminf(cx2, x2) - fmaxf(cx1, x1) + 1.f, 0.f);
            float ih = fmaxf(fminf(cy2, y2) - fmaxf(cy1, y1) + 1.f, 0.f);
            float inter = iw * ih;
            float iou = inter / (ca + (x2 - x1 + 1.f)*(y2 - y1 + 1.f) - inter);
            if (iou > 0.7f) atomicOr(&rm[j >> 5], 1u << (j & 31));
        }
        __syncthreads();
    }
    for (int k = cnt + tid; k < POST; k += blockDim.x) g_sel[b*POST + k] = 0;
}

__global__ void rois_kernel(float* __restrict__ out) {
    int t = blockIdx.x * blockDim.x + threadIdx.x;
    if (t >= 2*POST) return;
    int b = t / POST, k = t % POST;
    int i = g_sel[b*POST + k];
    size_t o = ((size_t)b*POST + k)*5;
    size_t src = ((size_t)b*PRE + i)*4;
    out[o+0] = (float)b;
    out[o+1] = g_topb[src+0]; out[o+2] = g_topb[src+1];
    out[o+3] = g_topb[src+2]; out[o+4] = g_topb[src+3];
}

// ---------------- anchor target: masked IoU, per-anchor max/argmax, per-GT max ---
__global__ void iou_kernel(const float* __restrict__ gt, const float* __restrict__ info) {
    int b = blockIdx.y;
    int i = blockIdx.x * blockDim.x + threadIdx.x;
    __shared__ float sgt[20][4];
    if (threadIdx.x < 80)
        ((float*)sgt)[threadIdx.x] = gt[b*100 + (threadIdx.x/4)*5 + (threadIdx.x%4)];
    __syncthreads();
    float infoH = info[b*3+0], infoW = info[b*3+1];
    bool act = i < NA;
    int a = act ? i % 9 : 0, hw = act ? i / 9 : 0;
    float gx = (hw % WW) * 16.f, gy = (hw / WW) * 16.f;
    float ax1 = c_anc[a][0]+gx, ay1 = c_anc[a][1]+gy, ax2 = c_anc[a][2]+gx, ay2 = c_anc[a][3]+gy;
    bool inside = act && (ax1 >= 0.f) && (ay1 >= 0.f) && (ax2 < infoW) && (ay2 < infoH);
    float areaA = (ax2 - ax1 + 1.f) * (ay2 - ay1 + 1.f);
    float best = -1e30f; int bi = 0;
    for (int g = 0; g < 20; ++g) {
        float bx1 = sgt[g][0], by1 = sgt[g][1], bx2 = sgt[g][2], by2 = sgt[g][3];
        float iw = fmaxf(fminf(ax2, bx2) - fmaxf(ax1, bx1) + 1.f, 0.f);
        float ih = fmaxf(fminf(ay2, by2) - fmaxf(ay1, by1) + 1.f, 0.f);
        float inter = iw * ih;
        float areaB = (bx2 - bx1 + 1.f) * (by2 - by1 + 1.f);
        float v = inter / (areaA + areaB - inter);
        v = inside ? v : -1.0f;
        if (act) {
            g_ov[((size_t)b*NA + i)*20 + g] = v;
            if (v > best) { best = v; bi = g; }
        }
        float vm = act ? v : -2.0f;
        #pragma unroll
        for (int off = 16; off; off >>= 1) vm = fmaxf(vm, __shfl_xor_sync(0xffffffffu, vm, off));
        if ((threadIdx.x & 31) == 0 && vm > 0.f)
            atomicMax(&g_gtmax[b*20 + g], __float_as_int(vm));
    }
    if (act) { g_maxov[(size_t)b*NA + i] = best; g_amax[(size_t)b*NA + i] = bi; }
}

__global__ void labels_kernel() {
    int b = blockIdx.y;
    int i = blockIdx.x * blockDim.x + threadIdx.x;
    if (i >= NA) return;
    float best = g_maxov[(size_t)b*NA + i];
    bool inside = g_ov[((size_t)b*NA + i)*20 + 0] >= 0.f;
    int lbl = -1;
    if (inside) {
        if (best < 0.3f) lbl = 0;
        bool isgt = false;
        for (int g = 0; g < 20; ++g) {
            float gm = __int_as_float(g_gtmax[b*20 + g]);
            if (gm > 0.f && g_ov[((size_t)b*NA + i)*20 + g] == gm) isgt = true;
        }
        if (isgt) lbl = 1;
        if (best >= 0.7f) lbl = 1;
    }
    g_labels[(size_t)b*NA + i] = lbl;
}

// ---------------- fg/bg subsample via inclusive block scan (1024 threads) --------
__global__ void cap_kernel() {
    int b = blockIdx.x;
    int tid = threadIdx.x, lane = tid & 31, wid = tid >> 5;
    __shared__ int wsum[32];
    __shared__ int s_carry, s_fg;
    int* lab = g_labels + (size_t)b*NA;
    if (tid == 0) s_carry = 0;
    __syncthreads();
    for (int base = 0; base < NA; base += 1024) {
        int i = base + tid;
        int f = (i < NA && lab[i] == 1) ? 1 : 0;
        int v = f;
        #pragma unroll
        for (int d = 1; d < 32; d <<= 1) { int n = __shfl_up_sync(0xffffffffu, v, d); if (lane >= d) v += n; }
        if (lane == 31) wsum[wid] = v;
        __syncthreads();
        if (wid == 0) {
            int t2 = wsum[lane];
            #pragma unroll
            for (int d = 1; d < 32; d <<= 1) { int n = __shfl_up_sync(0xffffffffu, t2, d); if (lane >= d) t2 += n; }
            wsum[lane] = t2;
        }
        __syncthreads();
        int pre = v + (wid ? wsum[wid-1] : 0) + s_carry;
        if (f && pre > 128) lab[i] = -1;
        __syncthreads();
        if (tid == 0) s_carry += wsum[31];
        __syncthreads();
    }
    if (tid == 0) { s_fg = min(s_carry, 128); s_carry = 0; }
    __syncthreads();
    int num_bg = 256 - s_fg;
    for (int base = 0; base < NA; base += 1024) {
        int i = base + tid;
        int f = (i < NA && lab[i] == 0) ? 1 : 0;
        int v = f;
        #pragma unroll
        for (int d = 1; d < 32; d <<= 1) { int n = __shfl_up_sync(0xffffffffu, v, d); if (lane >= d) v += n; }
        if (lane == 31) wsum[wid] = v;
        __syncthreads();
        if (wid == 0) {
            int t2 = wsum[lane];
            #pragma unroll
            for (int d = 1; d < 32; d <<= 1) { int n = __shfl_up_sync(0xffffffffu, t2, d); if (lane >= d) t2 += n; }
            wsum[lane] = t2;
        }
        __syncthreads();
        int pre = v + (wid ? wsum[wid-1] : 0) + s_carry;
        if (f && pre > num_bg) lab[i] = -1;
        __syncthreads();
        if (tid == 0) s_carry += wsum[31];
        __syncthreads();
    }
    if (tid == 0) g_cnt[b] = s_fg + min(s_carry, num_bg);
}

// ---------------- losses: deterministic single-block reduction ----------------
__global__ void loss_kernel(float* __restrict__ out, const float* __restrict__ gt) {
    int tid = threadIdx.x;
    __shared__ float scl[1024], sr0[1024], sr1[1024];
    float cl = 0.f, r0 = 0.f, r1 = 0.f;
    for (int t = tid; t < 2*NA; t += 1024) {
        int b = t / NA, i = t % NA;
        int lab = g_labels[(size_t)b*NA + i];
        if (lab == -1) continue;
        int a = i % 9, hw = i / 9;
        float s0 = g_cls[((size_t)b*18 + a)*HW + hw];
        float s1 = g_cls[((size_t)b*18 + 9 + a)*HW + hw];
        float m = fmaxf(s0, s1);
        float lse = m + logf(expf(s0 - m) + expf(s1 - m));
        cl += (lab ? s1 : s0) - lse;
        if (lab == 1) {
            float gx = (hw % WW) * 16.f, gy = (hw / WW) * 16.f;
            float ax1 = c_anc[a][0]+gx, ay1 = c_anc[a][1]+gy;
            float ax2 = c_anc[a][2]+gx, ay2 = c_anc[a][3]+gy;
            float ew = ax2-ax1+1.f, eh = ay2-ay1+1.f;
            float ecx = ax1 + 0.5f*ew, ecy = ay1 + 0.5f*eh;
            int g = g_amax[(size_t)b*NA + i];
            const float* G = gt + b*100 + g*5;
            float gw = G[2]-G[0]+1.f, gh = G[3]-G[1]+1.f;
            float gcx = G[0]+0.5f*gw, gcy = G[1]+0.5f*gh;
            float tgt[4] = { (gcx-ecx)/ew, (gcy-ecy)/eh, logf(gw/ew), logf(gh/eh) };
            float s = 0.f;
            #pragma unroll
            for (int j = 0; j < 4; ++j) {
                float p = g_reg[((size_t)b*36 + a*4 + j)*HW + hw];
                float d = p - tgt[j];
                float ad = fabsf(d);
                s += (ad < 1.f/9.f) ? 4.5f*d*d : (ad - 1.f/18.f);
            }
            if (b) r1 += s; else r0 += s;
        }
    }
    scl[tid] = cl; sr0[tid] = r0; sr1[tid] = r1;
    __syncthreads();
    for (int s = 512; s; s >>= 1) {
        if (tid < s) { scl[tid]+=scl[tid+s]; sr0[tid]+=sr0[tid+s]; sr1[tid]+=sr1[tid+s]; }
        __syncthreads();
    }
    if (tid == 0) {
        int cnt = g_cnt[0] + g_cnt[1];
        out[2*POST*5 + 0] = -scl[0] / (float)max(cnt, 1);
        float ne0 = fmaxf((float)g_cnt[0], 1.f), ne1 = fmaxf((float)g_cnt[1], 1.f);
        out[2*POST*5 + 1] = 0.5f * (sr0[0]/ne0 + sr1[0]/ne1);
    }
}

extern "C" void kernel_launch(void* const* d_in, const int* in_sizes, int n_in,
                              void* d_out, int out_size) {
    const float* feat = (const float*)d_in[0];
    const float* gt   = (const float*)d_in[1];
    const float* info = (const float*)d_in[2];
    const float* wc   = (const float*)d_in[3];
    const float* bc   = (const float*)d_in[4];
    const float* wcl  = (const float*)d_in[5];
    const float* bcl  = (const float*)d_in[6];
    const float* wrg  = (const float*)d_in[7];
    const float* brg  = (const float*)d_in[8];
    float* out = (float*)d_out;

    init_kernel<<<1, 64>>>();
    conv3_kernel<<<dim3(38, 8, 2), 256>>>(feat, wc, bc);
    heads_kernel<<<2*HW, 64>>>(wcl, bcl, wrg, brg);
    scorebox_kernel<<<dim3(NS/256, 2), 256>>>(info);
    sort_local_kernel<<<dim3(8, 2), 512>>>();
    for (int k = 8192; k <= NS; k <<= 1) {
        for (int j = k >> 1; j >= 4096; j >>= 1)
            sort_global_kernel<<<dim3(NS/256, 2), 256>>>(k, j);
        sort_merge_kernel<<<dim3(8, 2), 512>>>(k);
    }
    gather_top_kernel<<<(2*PRE + 255)/256, 256>>>();
    nms_kernel<<<2, 256>>>();
    rois_kernel<<<3, 256>>>(out);
    iou_kernel<<<dim3((NA + 255)/256, 2), 256>>>(gt, info);
    labels_kernel<<<dim3((NA + 255)/256, 2), 256>>>();
    cap_kernel<<<2, 1024>>>();
    loss_kernel<<<1, 1024>>>(out, gt);
}